// round 10
// baseline (speedup 1.0000x reference)
#include <cuda_runtime.h>

#define BB 8
#define CC 14
#define HH 512
#define WW 512
#define PP (HH * WW)          // 262144 = 2^18
#define KK 13                 // classes 1..13
#define NBK (BB * KK)         // 104
#define THREADS 256
#define GRID_BLOCKS ((BB * PP) / THREADS)   // 8192
#define DEPTH 6               // software-pipeline depth (channels prefetched)

// Global scratch. Zero-initialized at module load; the last block resets
// them after consuming, so every invocation starts from zeros.
__device__ float        g_kl[NBK];
__device__ unsigned int g_n[NBK];
__device__ unsigned int g_flag[NBK];
__device__ unsigned int g_count;

__global__ void __launch_bounds__(THREADS, 8) bkd_fused_kernel(
    const float* __restrict__ S,
    const float* __restrict__ T,
    const int*   __restrict__ gt,
    float*       __restrict__ out)
{
    __shared__ float        s_kl[KK];
    __shared__ unsigned int s_n[KK];
    __shared__ unsigned int s_flag[KK];
    __shared__ unsigned int s_isLast;
    if (threadIdx.x < KK) {
        s_kl[threadIdx.x]   = 0.0f;
        s_n[threadIdx.x]    = 0u;
        s_flag[threadIdx.x] = 0u;
    }
    __syncthreads();

    const int tid  = blockIdx.x * blockDim.x + threadIdx.x;
    const int b    = tid >> 18;               // / PP  (1 pixel per thread)
    const int hw   = tid & (PP - 1);
    const int h    = hw >> 9;                 // / 512
    const int w    = hw & 511;
    const int lane = threadIdx.x & 31;

    const float* Sp = S + (size_t)b * CC * PP + hw;
    const float* Tp = T + (size_t)b * CC * PP + hw;

    // ---- prime the pipeline: issue first DEPTH channels of loads ----
    float bs[DEPTH], bt[DEPTH];
#pragma unroll
    for (int i = 0; i < DEPTH; i++) {
        bs[i] = __ldcs(Sp + (size_t)i * PP);
        bt[i] = __ldcs(Tp + (size_t)i * PP);
    }

    // ---- boundary detection (overlaps with in-flight S/T loads) ----
    // Rows are 512 px and warps are 32-aligned, so w==0 only at lane 0 and
    // w==511 only at lane 31: left/right neighbors come from shfl except at
    // warp edges.
    const int* gtb = gt + (size_t)b * PP;
    const int g  = gtb[hw];
    const int gu = (h > 0)      ? gtb[hw - WW] : -1;
    const int gd = (h < HH - 1) ? gtb[hw + WW] : -1;

    int gl = __shfl_up_sync(0xffffffffu, g, 1);
    int gr = __shfl_down_sync(0xffffffffu, g, 1);
    if (lane == 0)  gl = (w > 0)      ? gtb[hw - 1] : -1;
    if (lane == 31) gr = (w < WW - 1) ? gtb[hw + 1] : -1;

    const bool bnd = (g >= 1) && (gu != g || gd != g || gl != g || gr != g);

    // ---- pipelined single-pass softmax/KL accumulation ----
    // kl = A/Z_T + log(Z_S/Z_T)
    float ZS = 0.f, ZT = 0.f, A = 0.f;

#pragma unroll
    for (int c = 0; c < CC; c++) {
        const int slot = c % DEPTH;           // constant after full unroll
        float xs = bs[slot];
        float xt = bt[slot];
        if (c + DEPTH < CC) {                 // issue next loads BEFORE compute
            bs[slot] = __ldcs(Sp + (size_t)(c + DEPTH) * PP);
            bt[slot] = __ldcs(Tp + (size_t)(c + DEPTH) * PP);
        }
        float es = __expf(xs), et = __expf(xt);
        ZS += es; ZT += et; A = fmaf(et, xt - xs, A);
    }

    // ---- per-block shared accumulation into 13 class bins ----
    if (bnd) {
        float r  = __fdividef(1.0f, ZT);
        float kl = A * r + __logf(ZS * r);
        int k = g - 1;
        atomicAdd(&s_kl[k], kl);
        atomicAdd(&s_n[k], 1u);
        if (hw > 0) s_flag[k] = 1u;           // idempotent racing write
    }
    __syncthreads();

    if (threadIdx.x < KK) {
        int k   = threadIdx.x;
        int idx = b * KK + k;
        if (s_n[k] > 0u) {
            atomicAdd(&g_kl[idx], s_kl[k]);
            atomicAdd(&g_n[idx],  s_n[k]);
        }
        if (s_flag[k]) atomicOr(&g_flag[idx], 1u);
    }

    // ---- last-block-done finalize (fused reduction + scratch reset) ----
    __threadfence();
    if (threadIdx.x == 0) {
        unsigned int v = atomicAdd(&g_count, 1u);
        s_isLast = (v == (unsigned int)(GRID_BLOCKS - 1)) ? 1u : 0u;
    }
    __syncthreads();

    if (s_isLast) {
        __shared__ float sred[256];
        int i = threadIdx.x;
        float t = 0.0f;
        if (i < NBK && g_flag[i]) {
            unsigned int n = g_n[i];
            if (n < 1u) n = 1u;
            t = g_kl[i] / (14.0f * (float)n);
        }
        sred[i] = t;
        __syncthreads();
#pragma unroll
        for (int s = 128; s > 0; s >>= 1) {
            if (i < s) sred[i] += sred[i + s];
            __syncthreads();
        }
        if (i == 0) {
            out[0] = sred[0];        // LOSS_WEIGHT * TAU^2 == 1
            g_count = 0u;            // reset for next replay
        }
        if (i < NBK) {
            g_kl[i]   = 0.0f;
            g_n[i]    = 0u;
            g_flag[i] = 0u;
        }
    }
}

extern "C" void kernel_launch(void* const* d_in, const int* in_sizes, int n_in,
                              void* d_out, int out_size) {
    const float* S  = (const float*)d_in[0];
    const float* T  = (const float*)d_in[1];
    const int*   gt = (const int*)d_in[2];
    float* out = (float*)d_out;

    bkd_fused_kernel<<<GRID_BLOCKS, THREADS>>>(S, T, gt, out);
}